// round 10
// baseline (speedup 1.0000x reference)
#include <cuda_runtime.h>
#include <cuda_bf16.h>

#define B_  16
#define N_  512
#define E_  32
#define HD  64

// Scratch: A[b][k][n] = H[b,n,:] @ W1[:32, k]
//          Bm[b][k][n] = H[b,n,:] @ W1[32:, k] + b1[k]
__device__ float g_A[B_ * HD * N_];
__device__ float g_Bm[B_ * HD * N_];

// Monotonic grid-barrier counter. Never reset: each kernel call adds exactly
// gridDim.x (576), and calls are stream-serialized, so every block derives the
// same target = (old/576 + 1)*576. Replay-safe, no sense flag, no race.
__device__ unsigned long long g_bar = 0ULL;

// ---------------------------------------------------------------------------
// smem: precompute scratch overlaps the pair tiles (phases separated by the
// grid barrier + __syncthreads). Total ~32.6 KB -> 4+ blocks/SM guaranteed.
// ---------------------------------------------------------------------------
struct SmemPre  { float sW[E_ * 32]; float sH[64 * 33]; };                 // 12.4 KB
struct SmemPair { float As[HD * 64]; unsigned long long Bs2[HD * 32]; };   // 32 KB
union  SmemU    { SmemPre pre; SmemPair pair; };

__device__ __forceinline__ unsigned long long dup_f32(float x)
{
    unsigned long long d;
    asm("mov.b64 %0, {%1, %1};" : "=l"(d) : "f"(x));
    return d;
}

// packed f32x2 inner step (proven form): ADD2, 2x FMNMX on halves, FFMA2
__device__ __forceinline__ void pair_step(unsigned long long& acc,
                                          unsigned long long a2,
                                          unsigned long long b2,
                                          unsigned long long w2)
{
    asm("{\n\t"
        ".reg .f32 lo, hi;\n\t"
        ".reg .b64 t, r;\n\t"
        "add.rn.f32x2 t, %1, %2;\n\t"
        "mov.b64 {lo, hi}, t;\n\t"
        "max.f32 lo, lo, 0f00000000;\n\t"
        "max.f32 hi, hi, 0f00000000;\n\t"
        "mov.b64 r, {lo, hi};\n\t"
        "fma.rn.f32x2 %0, r, %3, %0;\n\t"
        "}"
        : "+l"(acc) : "l"(a2), "l"(b2), "l"(w2));
}

// ---------------------------------------------------------------------------
// Fused kernel: precompute (blocks 0..511) -> grid barrier -> pair MLP (all).
// ---------------------------------------------------------------------------
__global__ void __launch_bounds__(256, 4) fused_kernel(
    const float* __restrict__ H,
    const float* __restrict__ W1,
    const float* __restrict__ b1,
    const float* __restrict__ W2,
    const float* __restrict__ b2g,
    float* __restrict__ out)
{
    __shared__ SmemU sm;
    __shared__ unsigned long long sw2d[HD];
    __shared__ float sb2;

    int tid = threadIdx.x;
    int bid = blockIdx.x;

    // weights prolog (region disjoint from sm union — no sync needed yet)
    if (tid < HD) sw2d[tid] = dup_f32(W2[tid]);
    if (tid == 0) sb2 = b2g[0];

    // ---- phase 1: precompute chunk (512 chunks over blocks 0..511) ----
    if (bid < 512) {
        int khalf  = bid & 1;          // k 0..31 / 32..63
        int which  = (bid >> 1) & 1;   // 0: A, 1: Bm
        int nChunk = (bid >> 2) & 7;
        int pb     = bid >> 5;         // batch

        const float* Wsrc = W1 + which * E_ * HD + khalf * 32;
        #pragma unroll
        for (int p = tid; p < E_ * 32; p += 256) {
            int r = p >> 5, c = p & 31;
            sm.pre.sW[p] = Wsrc[r * HD + c];
        }
        int nBase = pb * N_ + nChunk * 64;
        #pragma unroll
        for (int p = tid; p < 64 * E_; p += 256) {
            int r = p >> 5, c = p & 31;
            sm.pre.sH[r * 33 + c] = H[nBase * E_ + p];
        }
        __syncthreads();

        int nL   = tid & 63;
        int kOff = (tid >> 6) * 8;

        float h[E_];
        #pragma unroll
        for (int e = 0; e < E_; e++) h[e] = sm.pre.sH[nL * 33 + e];

        float* dst = which ? g_Bm : g_A;
        #pragma unroll
        for (int kk = 0; kk < 8; kk++) {
            int kq = kOff + kk;
            int k  = khalf * 32 + kq;
            float acc = which ? b1[k] : 0.0f;
            #pragma unroll
            for (int e = 0; e < E_; e++)
                acc = fmaf(h[e], sm.pre.sW[e * 32 + kq], acc);
            dst[(pb * HD + k) * N_ + nChunk * 64 + nL] = acc;
        }
    }

    // ---- grid barrier (monotonic counter; all 576 blocks co-resident) ----
    __syncthreads();                       // all block stores ordered before publish
    if (tid == 0) {
        __threadfence();                   // publish this block's g_A/g_Bm writes
        unsigned long long old = atomicAdd(&g_bar, 1ULL);
        unsigned long long target = (old / 576ULL + 1ULL) * 576ULL;
        while (*(volatile unsigned long long*)&g_bar < target) { }
        __threadfence();                   // acquire side
    }
    __syncthreads();

    // ---- phase 2: pair MLP over 64x64 upper-triangle tiles ----
    int b = bid & 15;
    int t = bid >> 4;                      // 0..35
    int ti = 0;
    while (t >= (8 - ti)) { t -= (8 - ti); ti++; }
    int tj = ti + t;                       // ti <= tj

    // Fill As (plain floats, k-major rows of 64)
    const float4* Ag4 = reinterpret_cast<const float4*>(g_A + (size_t)b * HD * N_ + ti * 64);
    #pragma unroll
    for (int p = 0; p < 4; p++) {
        int idx = tid + p * 256;           // 0..1023 float4 slots
        int k = idx >> 4, q = idx & 15;
        *reinterpret_cast<float4*>(&sm.pair.As[(k << 6) + (q << 2)]) = Ag4[k * (N_ / 4) + q];
    }
    // Fill Bs2: adjacent-j pairs, interleaved: pair jp -> (jp&1)*16 + (jp>>1)
    const float2* Bg = reinterpret_cast<const float2*>(g_Bm + (size_t)b * HD * N_ + tj * 64);
    #pragma unroll
    for (int p = 0; p < 8; p++) {
        int idx = tid + p * 256;           // 0..2047
        int k = idx >> 5, jp = idx & 31;
        float2 v = Bg[k * (N_ / 2) + jp];
        int pos = ((jp & 1) << 4) | (jp >> 1);
        sm.pair.Bs2[(k << 5) + pos] = *reinterpret_cast<unsigned long long*>(&v);
    }
    __syncthreads();

    int ty = tid >> 4, tx = tid & 15;

    unsigned long long acc[4][2];
    {
        unsigned long long bi = dup_f32(sb2);
        #pragma unroll
        for (int r = 0; r < 4; r++) { acc[r][0] = bi; acc[r][1] = bi; }
    }

    const float* Apf = sm.pair.As + (ty << 2);

    #pragma unroll 8
    for (int k = 0; k < HD; k++) {
        unsigned long long w2  = sw2d[k];                     // LDS.64 bcast
        unsigned long long b0  = sm.pair.Bs2[(k << 5) + tx];       // (4tx, 4tx+1)
        unsigned long long b1v = sm.pair.Bs2[(k << 5) + 16 + tx];  // (4tx+2, 4tx+3)
        float2 a01 = *reinterpret_cast<const float2*>(Apf + (k << 6));      // LDS.64
        float2 a23 = *reinterpret_cast<const float2*>(Apf + (k << 6) + 2);  // LDS.64
        unsigned long long a0d = dup_f32(a01.x);
        unsigned long long a1d = dup_f32(a01.y);
        unsigned long long a2d = dup_f32(a23.x);
        unsigned long long a3d = dup_f32(a23.y);
        pair_step(acc[0][0], a0d, b0, w2);
        pair_step(acc[0][1], a0d, b1v, w2);
        pair_step(acc[1][0], a1d, b0, w2);
        pair_step(acc[1][1], a1d, b1v, w2);
        pair_step(acc[2][0], a2d, b0, w2);
        pair_step(acc[2][1], a2d, b1v, w2);
        pair_step(acc[3][0], a3d, b0, w2);
        pair_step(acc[3][1], a3d, b1v, w2);
    }

    // sigmoid epilogue
    float p[4][4];
    #pragma unroll
    for (int r = 0; r < 4; r++)
        #pragma unroll
        for (int cp = 0; cp < 2; cp++) {
            float lo, hi;
            asm("mov.b64 {%0, %1}, %2;" : "=f"(lo), "=f"(hi) : "l"(acc[r][cp]));
            p[r][cp * 2 + 0] = 1.0f / (1.0f + __expf(-lo));
            p[r][cp * 2 + 1] = 1.0f / (1.0f + __expf(-hi));
        }

    int i0 = ti * 64 + ty * 4;
    int j0 = tj * 64 + tx * 4;
    float* outb = out + (size_t)b * N_ * N_;

    if (ti != tj) {
        #pragma unroll
        for (int r = 0; r < 4; r++) {
            float4 v = make_float4(p[r][0], p[r][1], p[r][2], p[r][3]);
            *reinterpret_cast<float4*>(outb + (size_t)(i0 + r) * N_ + j0) = v;
        }
        #pragma unroll
        for (int c = 0; c < 4; c++) {
            float4 v = make_float4(p[0][c], p[1][c], p[2][c], p[3][c]);
            *reinterpret_cast<float4*>(outb + (size_t)(j0 + c) * N_ + i0) = v;
        }
    } else {
        #pragma unroll
        for (int r = 0; r < 4; r++)
            #pragma unroll
            for (int c = 0; c < 4; c++) {
                int i = i0 + r, j = j0 + c;
                if (i < j) {
                    float v = p[r][c];
                    outb[(size_t)i * N_ + j] = v;
                    outb[(size_t)j * N_ + i] = v;
                } else if (i == j) {
                    outb[(size_t)i * N_ + j] = 0.0f;
                }
            }
    }
}

extern "C" void kernel_launch(void* const* d_in, const int* in_sizes, int n_in,
                              void* d_out, int out_size)
{
    const float* H  = (const float*)d_in[0];   // node_emb [8192, 32]
    const float* W1 = (const float*)d_in[1];   // [64, 64]
    const float* b1 = (const float*)d_in[2];   // [64]
    const float* W2 = (const float*)d_in[3];   // [64]
    const float* b2 = (const float*)d_in[4];   // [1]
    float* out = (float*)d_out;                // [16, 512, 512]

    fused_kernel<<<576, 256>>>(H, W1, b1, W2, b2, out);
}